// round 2
// baseline (speedup 1.0000x reference)
#include <cuda_runtime.h>

#define Nn  50000
#define HID 64
#define Ee  800000
#define EPn 100000
#define BN_EPS 1e-5f

// ---------------- scratch (static device globals; no allocation) ----------------
__device__ float g_x[Nn * HID];     // node features (running)
__device__ float g_h[Nn * HID];     // x @ conv_w[l]
__device__ float g_agg[Nn * HID];   // aggregated messages
__device__ float g_dis[Nn];         // deg, then d^{-1/2}
__device__ float g_stats[2 * HID];  // BN: [sum | sumsq]

// ---------------- degree / norm ----------------
__global__ void k_deg_init() {
    int i = blockIdx.x * blockDim.x + threadIdx.x;
    if (i < Nn) g_dis[i] = 1.0f;  // self-loop contributes 1 to in-degree
}

__global__ void k_deg_count(const int* __restrict__ col) {
    int e = blockIdx.x * blockDim.x + threadIdx.x;
    if (e < Ee) atomicAdd(&g_dis[col[e]], 1.0f);
}

__global__ void k_deg_rsqrt() {
    int i = blockIdx.x * blockDim.x + threadIdx.x;
    if (i < Nn) g_dis[i] = rsqrtf(g_dis[i]);  // deg >= 1 always
}

// ---------------- input projection: x = [id|n2v] @ proj_w + proj_b ----------------
// 64x64 output tile per block, 4x4 register blocking. K=128 processed as two
// K=64 phases (phase 0: id_emb x pw[0:64,:], phase 1: n2v x pw[64:128,:]) so
// static smem stays at 32KB (<48KB limit).
__global__ __launch_bounds__(256) void k_proj(
    const float* __restrict__ id_emb, const float* __restrict__ n2v,
    const float* __restrict__ pw, const float* __restrict__ pb)
{
    __shared__ float s_a[64 * 64];   // input tile, row-major [r][k]
    __shared__ float s_w[64 * 64];   // weight tile [k][c]
    const int tid = threadIdx.x;
    const int rb  = blockIdx.x;
    const int tc = tid & 15, tr = tid >> 4;

    float acc[4][4];
#pragma unroll
    for (int i = 0; i < 4; i++)
#pragma unroll
        for (int j = 0; j < 4; j++) acc[i][j] = 0.f;

#pragma unroll
    for (int ph = 0; ph < 2; ph++) {
        const float* src = ph ? n2v : id_emb;
        const float* wsrc = pw + ph * 64 * 64;
        for (int i = tid; i < 64 * 64; i += 256) s_w[i] = wsrc[i];
        for (int i = tid; i < 64 * 64; i += 256) {
            int r = i >> 6, k = i & 63;
            int row = rb * 64 + r;
            s_a[i] = (row < Nn) ? src[row * 64 + k] : 0.f;
        }
        __syncthreads();

        const float4* w4 = reinterpret_cast<const float4*>(s_w);
#pragma unroll 8
        for (int k = 0; k < 64; k++) {
            float4 wv = w4[k * 16 + tc];
            float a0 = s_a[(tr * 4 + 0) * 64 + k];
            float a1 = s_a[(tr * 4 + 1) * 64 + k];
            float a2 = s_a[(tr * 4 + 2) * 64 + k];
            float a3 = s_a[(tr * 4 + 3) * 64 + k];
            acc[0][0] += a0 * wv.x; acc[0][1] += a0 * wv.y; acc[0][2] += a0 * wv.z; acc[0][3] += a0 * wv.w;
            acc[1][0] += a1 * wv.x; acc[1][1] += a1 * wv.y; acc[1][2] += a1 * wv.z; acc[1][3] += a1 * wv.w;
            acc[2][0] += a2 * wv.x; acc[2][1] += a2 * wv.y; acc[2][2] += a2 * wv.z; acc[2][3] += a2 * wv.w;
            acc[3][0] += a3 * wv.x; acc[3][1] += a3 * wv.y; acc[3][2] += a3 * wv.z; acc[3][3] += a3 * wv.w;
        }
        __syncthreads();
    }

    float4 bv = reinterpret_cast<const float4*>(pb)[tc];
#pragma unroll
    for (int i = 0; i < 4; i++) {
        int row = rb * 64 + tr * 4 + i;
        if (row < Nn) {
            float4 o;
            o.x = acc[i][0] + bv.x; o.y = acc[i][1] + bv.y;
            o.z = acc[i][2] + bv.z; o.w = acc[i][3] + bv.w;
            *reinterpret_cast<float4*>(&g_x[row * 64 + tc * 4]) = o;
        }
    }
}

// ---------------- conv GEMM: h = x @ w (64x64), no bias ----------------
__global__ __launch_bounds__(256) void k_gemm64(const float* __restrict__ w)
{
    __shared__ float s_a[64 * 64];
    __shared__ float s_w[64 * 64];
    const int tid = threadIdx.x;
    const int rb  = blockIdx.x;

    for (int i = tid; i < 64 * 64; i += 256) s_w[i] = w[i];
    for (int i = tid; i < 64 * 64; i += 256) {
        int r = i >> 6, k = i & 63;
        int row = rb * 64 + r;
        s_a[i] = (row < Nn) ? g_x[row * 64 + k] : 0.f;
    }
    __syncthreads();

    const int tc = tid & 15, tr = tid >> 4;
    float acc[4][4];
#pragma unroll
    for (int i = 0; i < 4; i++)
#pragma unroll
        for (int j = 0; j < 4; j++) acc[i][j] = 0.f;

    const float4* w4 = reinterpret_cast<const float4*>(s_w);
#pragma unroll 8
    for (int k = 0; k < 64; k++) {
        float4 wv = w4[k * 16 + tc];
        float a0 = s_a[(tr * 4 + 0) * 64 + k];
        float a1 = s_a[(tr * 4 + 1) * 64 + k];
        float a2 = s_a[(tr * 4 + 2) * 64 + k];
        float a3 = s_a[(tr * 4 + 3) * 64 + k];
        acc[0][0] += a0 * wv.x; acc[0][1] += a0 * wv.y; acc[0][2] += a0 * wv.z; acc[0][3] += a0 * wv.w;
        acc[1][0] += a1 * wv.x; acc[1][1] += a1 * wv.y; acc[1][2] += a1 * wv.z; acc[1][3] += a1 * wv.w;
        acc[2][0] += a2 * wv.x; acc[2][1] += a2 * wv.y; acc[2][2] += a2 * wv.z; acc[2][3] += a2 * wv.w;
        acc[3][0] += a3 * wv.x; acc[3][1] += a3 * wv.y; acc[3][2] += a3 * wv.z; acc[3][3] += a3 * wv.w;
    }

#pragma unroll
    for (int i = 0; i < 4; i++) {
        int row = rb * 64 + tr * 4 + i;
        if (row < Nn) {
            float4 o;
            o.x = acc[i][0]; o.y = acc[i][1]; o.z = acc[i][2]; o.w = acc[i][3];
            *reinterpret_cast<float4*>(&g_h[row * 64 + tc * 4]) = o;
        }
    }
}

// ---------------- agg init: bias + self-loop term; also zero BN stats ----------------
__global__ void k_agg_init(const float* __restrict__ cb)
{
    int t = blockIdx.x * blockDim.x + threadIdx.x;
    if (t < 2 * HID) g_stats[t] = 0.f;
    if (t < Nn * HID) {
        int row = t >> 6, f = t & 63;
        float d = g_dis[row];
        g_agg[t] = cb[f] + d * d * g_h[t];
    }
}

// ---------------- edge scatter: agg[col] += norm * h[row]  (16 thr/edge, float4) ----------------
__global__ void k_scatter(const int* __restrict__ rowi, const int* __restrict__ coli)
{
    int t = blockIdx.x * blockDim.x + threadIdx.x;
    int e = t >> 4;
    if (e >= Ee) return;
    int f = (t & 15) << 2;
    int r = __ldg(rowi + e);
    int c = __ldg(coli + e);
    float nrm = __ldg(&g_dis[r]) * __ldg(&g_dis[c]);
    float4 hv = *reinterpret_cast<const float4*>(&g_h[r * HID + f]);
    float* dst = &g_agg[c * HID + f];
    asm volatile("red.global.add.v4.f32 [%0], {%1,%2,%3,%4};"
                 :: "l"(dst), "f"(nrm * hv.x), "f"(nrm * hv.y),
                    "f"(nrm * hv.z), "f"(nrm * hv.w)
                 : "memory");
}

// ---------------- BN stats: per-column sum / sumsq ----------------
__global__ __launch_bounds__(256) void k_stats()
{
    const int c  = threadIdx.x & 63;
    const int rl = threadIdx.x >> 6;  // 0..3
    float s = 0.f, s2 = 0.f;
    for (int row = blockIdx.x * 4 + rl; row < Nn; row += gridDim.x * 4) {
        float v = g_agg[row * HID + c];
        s += v; s2 += v * v;
    }
    __shared__ float ss[4][64], ss2[4][64];
    ss[rl][c] = s; ss2[rl][c] = s2;
    __syncthreads();
    if (rl == 0) {
        s  = ss[0][c]  + ss[1][c]  + ss[2][c]  + ss[3][c];
        s2 = ss2[0][c] + ss2[1][c] + ss2[2][c] + ss2[3][c];
        atomicAdd(&g_stats[c], s);
        atomicAdd(&g_stats[64 + c], s2);
    }
}

// ---------------- BN apply + ReLU + residual ----------------
__global__ void k_apply(const float* __restrict__ gamma, const float* __restrict__ beta)
{
    int t = blockIdx.x * blockDim.x + threadIdx.x;
    if (t >= Nn * HID) return;
    int f = t & 63;
    const float invN = 1.0f / (float)Nn;
    float mu  = g_stats[f] * invN;
    float var = g_stats[64 + f] * invN - mu * mu;
    float xn = (g_agg[t] - mu) * rsqrtf(var + BN_EPS) * gamma[f] + beta[f];
    g_x[t] += fmaxf(xn, 0.f);
}

// ---------------- decoder: out[p] = dot(z[a], z[b]) ----------------
__global__ void k_decode(const int* __restrict__ pe, float* __restrict__ out)
{
    int t = blockIdx.x * blockDim.x + threadIdx.x;
    int w = t >> 5, lane = t & 31;
    if (w >= EPn) return;
    int a = __ldg(pe + 2 * w);
    int b = __ldg(pe + 2 * w + 1);
    float acc = g_x[a * HID + lane]      * g_x[b * HID + lane]
              + g_x[a * HID + 32 + lane] * g_x[b * HID + 32 + lane];
#pragma unroll
    for (int o = 16; o; o >>= 1) acc += __shfl_xor_sync(0xffffffffu, acc, o);
    if (lane == 0) out[w] = acc;
}

// ---------------- launch ----------------
extern "C" void kernel_launch(void* const* d_in, const int* in_sizes, int n_in,
                              void* d_out, int out_size)
{
    const int*   edge   = (const int*)d_in[0];   // [2, E]
    const int*   rowi   = edge;                  // edge_index[0] (src)
    const int*   coli   = edge + Ee;             // edge_index[1] (dst)
    const int*   pe     = (const int*)d_in[1];   // [EP, 2]
    const float* id_emb = (const float*)d_in[2];
    const float* n2v    = (const float*)d_in[3];
    const float* pw     = (const float*)d_in[4];
    const float* pb     = (const float*)d_in[5];
    const float* cw     = (const float*)d_in[6]; // [L, 64, 64]
    const float* cb     = (const float*)d_in[7]; // [L, 64]
    const float* gamma  = (const float*)d_in[8]; // [L, 64]
    const float* beta   = (const float*)d_in[9]; // [L, 64]
    float*       out    = (float*)d_out;

    const int TB = 256;

    k_deg_init <<<(Nn + TB - 1) / TB, TB>>>();
    k_deg_count<<<(Ee + TB - 1) / TB, TB>>>(coli);
    k_deg_rsqrt<<<(Nn + TB - 1) / TB, TB>>>();

    k_proj<<<(Nn + 63) / 64, 256>>>(id_emb, n2v, pw, pb);

    for (int l = 0; l < 2; l++) {
        k_gemm64  <<<(Nn + 63) / 64, 256>>>(cw + l * HID * HID);
        k_agg_init<<<(Nn * HID + TB - 1) / TB, TB>>>(cb + l * HID);
        k_scatter <<<(Ee * 16 + TB - 1) / TB, TB>>>(rowi, coli);
        k_stats   <<<256, 256>>>();
        k_apply   <<<(Nn * HID + TB - 1) / TB, TB>>>(gamma + l * HID, beta + l * HID);
    }

    k_decode<<<(EPn * 32 + TB - 1) / TB, TB>>>(pe, out);
}

// round 4
// speedup vs baseline: 1.2917x; 1.2917x over previous
#include <cuda_runtime.h>

#define Nn  50000
#define HID 64
#define Ee  800000
#define EPn 100000
#define BN_EPS 1e-5f
#define PAD 68

// ---------------- scratch ----------------
__device__ float g_x[Nn * HID];
__device__ float g_h[Nn * HID];
__device__ float g_agg[Nn * HID];
__device__ float g_dis[Nn];
__device__ float g_stats[4 * HID];   // [l0 sum | l0 sumsq | l1 sum | l1 sumsq]

// ---------------- degree / init ----------------
__global__ void k_deg_init() {
    int i = blockIdx.x * blockDim.x + threadIdx.x;
    if (i < 4 * HID) g_stats[i] = 0.f;
    if (i < Nn) g_dis[i] = 1.0f;   // self-loop
}

__global__ void k_deg_count(const int* __restrict__ col) {
    int e = blockIdx.x * blockDim.x + threadIdx.x;
    if (e < Ee) atomicAdd(&g_dis[col[e]], 1.0f);
}

__global__ void k_deg_rsqrt() {
    int i = blockIdx.x * blockDim.x + threadIdx.x;
    if (i < Nn) g_dis[i] = rsqrtf(g_dis[i]);
}

// ---------------- shared GEMM pieces ----------------
// A tile stored transposed: element (row r, col k) at sa[k*PAD + (r ^ (k&28))].
// The XOR swizzle keeps 4-row groups intact (float4 reads stay aligned) while
// spreading column-major stores across banks.

__device__ __forceinline__ void load_AT(float* sa, const float* __restrict__ g,
                                        int rb, int tid) {
    for (int i = tid; i < 1024; i += 256) {
        int r = i >> 4, kq = (i & 15) << 2;
        int row = rb * 64 + r;
        float4 v = make_float4(0.f, 0.f, 0.f, 0.f);
        if (row < Nn) v = *reinterpret_cast<const float4*>(g + row * 64 + kq);
        int p = r ^ (kq & 28);
        sa[(kq + 0) * PAD + p] = v.x;
        sa[(kq + 1) * PAD + p] = v.y;
        sa[(kq + 2) * PAD + p] = v.z;
        sa[(kq + 3) * PAD + p] = v.w;
    }
}

__device__ __forceinline__ void load_W(float* sw, const float* __restrict__ w, int tid) {
    for (int i = tid; i < 1024; i += 256)
        reinterpret_cast<float4*>(sw)[i] = reinterpret_cast<const float4*>(w)[i];
}

__device__ __forceinline__ void mm64(const float* sa, const float* sw,
                                     int tc, int tr, float acc[4][4]) {
    const float4* w4 = reinterpret_cast<const float4*>(sw);
#pragma unroll 8
    for (int k = 0; k < 64; k++) {
        float4 av = *reinterpret_cast<const float4*>(&sa[k * PAD + ((tr * 4) ^ (k & 28))]);
        float4 wv = w4[k * 16 + tc];
        acc[0][0] += av.x * wv.x; acc[0][1] += av.x * wv.y; acc[0][2] += av.x * wv.z; acc[0][3] += av.x * wv.w;
        acc[1][0] += av.y * wv.x; acc[1][1] += av.y * wv.y; acc[1][2] += av.y * wv.z; acc[1][3] += av.y * wv.w;
        acc[2][0] += av.z * wv.x; acc[2][1] += av.z * wv.y; acc[2][2] += av.z * wv.z; acc[2][3] += av.z * wv.w;
        acc[3][0] += av.w * wv.x; acc[3][1] += av.w * wv.y; acc[3][2] += av.w * wv.z; acc[3][3] += av.w * wv.w;
    }
}

__device__ __forceinline__ void zero_acc(float acc[4][4]) {
#pragma unroll
    for (int i = 0; i < 4; i++)
#pragma unroll
        for (int j = 0; j < 4; j++) acc[i][j] = 0.f;
}

// epilogue: write h and agg = cb + d^2 * h
__device__ __forceinline__ void epilogue_h_agg(const float acc[4][4], const float* __restrict__ cb,
                                               int rb, int tc, int tr) {
    float4 cbv = reinterpret_cast<const float4*>(cb)[tc];
#pragma unroll
    for (int i = 0; i < 4; i++) {
        int row = rb * 64 + tr * 4 + i;
        if (row < Nn) {
            float d = g_dis[row];
            float d2 = d * d;
            float4 h = make_float4(acc[i][0], acc[i][1], acc[i][2], acc[i][3]);
            *reinterpret_cast<float4*>(&g_h[row * 64 + tc * 4]) = h;
            float4 a = make_float4(cbv.x + d2 * h.x, cbv.y + d2 * h.y,
                                   cbv.z + d2 * h.z, cbv.w + d2 * h.w);
            *reinterpret_cast<float4*>(&g_agg[row * 64 + tc * 4]) = a;
        }
    }
}

// ---------------- fused proj + conv0 + agg-init ----------------
__global__ __launch_bounds__(256) void k_proj_gemm0(
    const float* __restrict__ id_emb, const float* __restrict__ n2v,
    const float* __restrict__ pw, const float* __restrict__ pb,
    const float* __restrict__ cw0, const float* __restrict__ cb0)
{
    __shared__ float sa[64 * PAD];
    __shared__ float sw[64 * 64];
    const int tid = threadIdx.x, rb = blockIdx.x;
    const int tc = tid & 15, tr = tid >> 4;

    float acc[4][4];
    zero_acc(acc);

    // projection phase 0: id_emb @ pw[0:64,:]
    load_AT(sa, id_emb, rb, tid);
    load_W(sw, pw, tid);
    __syncthreads();
    mm64(sa, sw, tc, tr, acc);
    __syncthreads();

    // projection phase 1: n2v @ pw[64:128,:]
    load_AT(sa, n2v, rb, tid);
    load_W(sw, pw + 64 * 64, tid);
    __syncthreads();
    mm64(sa, sw, tc, tr, acc);
    __syncthreads();

    // x = acc + bias; write g_x; re-stage x into sa (transposed+swizzled)
    float4 bv = reinterpret_cast<const float4*>(pb)[tc];
#pragma unroll
    for (int i = 0; i < 4; i++) {
        acc[i][0] += bv.x; acc[i][1] += bv.y; acc[i][2] += bv.z; acc[i][3] += bv.w;
        int row = rb * 64 + tr * 4 + i;
        if (row < Nn)
            *reinterpret_cast<float4*>(&g_x[row * 64 + tc * 4]) =
                make_float4(acc[i][0], acc[i][1], acc[i][2], acc[i][3]);
    }
    {
        int s4 = (tc * 4) & 28;
#pragma unroll
        for (int j = 0; j < 4; j++)
#pragma unroll
            for (int i = 0; i < 4; i++)
                sa[(tc * 4 + j) * PAD + ((tr * 4 + i) ^ s4)] = acc[i][j];
    }
    load_W(sw, cw0, tid);
    __syncthreads();

    // conv0: h = x @ cw0
    zero_acc(acc);
    mm64(sa, sw, tc, tr, acc);
    epilogue_h_agg(acc, cb0, rb, tc, tr);
}

// ---------------- fused BN(l-1)+relu+residual + conv GEMM + agg-init ----------------
__global__ __launch_bounds__(256) void k_gemm_bn(
    const float* __restrict__ w, const float* __restrict__ cb,
    int stats_off, const float* __restrict__ gamma,
    const float* __restrict__ beta)
{
    __shared__ float sa[64 * PAD];
    __shared__ float sw[64 * 64];
    __shared__ float s_scale[64], s_shift[64];
    const int tid = threadIdx.x, rb = blockIdx.x;
    const int tc = tid & 15, tr = tid >> 4;

    if (tid < 64) {
        const float invN = 1.0f / (float)Nn;
        float mu = g_stats[stats_off + tid] * invN;
        float var = g_stats[stats_off + 64 + tid] * invN - mu * mu;
        float sc = rsqrtf(var + BN_EPS) * gamma[tid];
        s_scale[tid] = sc;
        s_shift[tid] = beta[tid] - mu * sc;
    }
    load_W(sw, w, tid);
    __syncthreads();

    // x_new = x + relu(bn(agg)); persist to g_x; stage into sa
    for (int i = tid; i < 1024; i += 256) {
        int r = i >> 4, kq = (i & 15) << 2;
        int row = rb * 64 + r;
        float4 v = make_float4(0.f, 0.f, 0.f, 0.f);
        if (row < Nn) {
            v = *reinterpret_cast<const float4*>(&g_x[row * 64 + kq]);
            float4 av = *reinterpret_cast<const float4*>(&g_agg[row * 64 + kq]);
            v.x += fmaxf(av.x * s_scale[kq + 0] + s_shift[kq + 0], 0.f);
            v.y += fmaxf(av.y * s_scale[kq + 1] + s_shift[kq + 1], 0.f);
            v.z += fmaxf(av.z * s_scale[kq + 2] + s_shift[kq + 2], 0.f);
            v.w += fmaxf(av.w * s_scale[kq + 3] + s_shift[kq + 3], 0.f);
            *reinterpret_cast<float4*>(&g_x[row * 64 + kq]) = v;
        }
        int p = r ^ (kq & 28);
        sa[(kq + 0) * PAD + p] = v.x;
        sa[(kq + 1) * PAD + p] = v.y;
        sa[(kq + 2) * PAD + p] = v.z;
        sa[(kq + 3) * PAD + p] = v.w;
    }
    __syncthreads();

    float acc[4][4];
    zero_acc(acc);
    mm64(sa, sw, tc, tr, acc);
    epilogue_h_agg(acc, cb, rb, tc, tr);
}

// ---------------- edge scatter ----------------
__global__ void k_scatter(const int* __restrict__ rowi, const int* __restrict__ coli)
{
    int t = blockIdx.x * blockDim.x + threadIdx.x;
    int e = t >> 4;
    if (e >= Ee) return;
    int f = (t & 15) << 2;
    int r = __ldg(rowi + e);
    int c = __ldg(coli + e);
    float nrm = __ldg(&g_dis[r]) * __ldg(&g_dis[c]);
    float4 hv = *reinterpret_cast<const float4*>(&g_h[r * HID + f]);
    float* dst = &g_agg[c * HID + f];
    asm volatile("red.global.add.v4.f32 [%0], {%1,%2,%3,%4};"
                 :: "l"(dst), "f"(nrm * hv.x), "f"(nrm * hv.y),
                    "f"(nrm * hv.z), "f"(nrm * hv.w)
                 : "memory");
}

// ---------------- BN stats ----------------
__global__ __launch_bounds__(256) void k_stats(int stats_off)
{
    const int tid = threadIdx.x;
    const int cq = (tid & 15) * 4, rl = tid >> 4;
    float4 s  = make_float4(0.f, 0.f, 0.f, 0.f);
    float4 s2 = make_float4(0.f, 0.f, 0.f, 0.f);
    for (int row = blockIdx.x * 16 + rl; row < Nn; row += gridDim.x * 16) {
        float4 v = *reinterpret_cast<const float4*>(&g_agg[row * 64 + cq]);
        s.x += v.x; s.y += v.y; s.z += v.z; s.w += v.w;
        s2.x += v.x * v.x; s2.y += v.y * v.y; s2.z += v.z * v.z; s2.w += v.w * v.w;
    }
    __shared__ float4 ss[16][16], ss2[16][16];
    ss[rl][tid & 15] = s;
    ss2[rl][tid & 15] = s2;
    __syncthreads();
    if (rl == 0) {
        float4 a = ss[0][tid & 15], b = ss2[0][tid & 15];
#pragma unroll
        for (int k = 1; k < 16; k++) {
            float4 u = ss[k][tid & 15], v = ss2[k][tid & 15];
            a.x += u.x; a.y += u.y; a.z += u.z; a.w += u.w;
            b.x += v.x; b.y += v.y; b.z += v.z; b.w += v.w;
        }
        float* so = g_stats + stats_off;
        atomicAdd(&so[cq + 0], a.x); atomicAdd(&so[cq + 1], a.y);
        atomicAdd(&so[cq + 2], a.z); atomicAdd(&so[cq + 3], a.w);
        atomicAdd(&so[64 + cq + 0], b.x); atomicAdd(&so[64 + cq + 1], b.y);
        atomicAdd(&so[64 + cq + 2], b.z); atomicAdd(&so[64 + cq + 3], b.w);
    }
}

// ---------------- final BN apply + relu + residual ----------------
__global__ __launch_bounds__(256) void k_apply(
    int stats_off, const float* __restrict__ gamma,
    const float* __restrict__ beta)
{
    __shared__ float s_scale[64], s_shift[64];
    if (threadIdx.x < 64) {
        const float invN = 1.0f / (float)Nn;
        float mu = g_stats[stats_off + threadIdx.x] * invN;
        float var = g_stats[stats_off + 64 + threadIdx.x] * invN - mu * mu;
        float sc = rsqrtf(var + BN_EPS) * gamma[threadIdx.x];
        s_scale[threadIdx.x] = sc;
        s_shift[threadIdx.x] = beta[threadIdx.x] - mu * sc;
    }
    __syncthreads();
    int t = blockIdx.x * blockDim.x + threadIdx.x;
    if (t >= Nn * 16) return;
    int f = (t & 15) * 4;
    float4 a = *reinterpret_cast<const float4*>(&g_agg[t * 4]);
    float4 x = *reinterpret_cast<float4*>(&g_x[t * 4]);
    x.x += fmaxf(a.x * s_scale[f + 0] + s_shift[f + 0], 0.f);
    x.y += fmaxf(a.y * s_scale[f + 1] + s_shift[f + 1], 0.f);
    x.z += fmaxf(a.z * s_scale[f + 2] + s_shift[f + 2], 0.f);
    x.w += fmaxf(a.w * s_scale[f + 3] + s_shift[f + 3], 0.f);
    *reinterpret_cast<float4*>(&g_x[t * 4]) = x;
}

// ---------------- decoder: 8 threads/edge, float4 ----------------
__global__ void k_decode(const int* __restrict__ pe, float* __restrict__ out)
{
    int t = blockIdx.x * blockDim.x + threadIdx.x;
    int e = t >> 3, sub = t & 7;
    if (e >= EPn) return;
    int a = __ldg(pe + 2 * e);
    int b = __ldg(pe + 2 * e + 1);
    const float4* za = reinterpret_cast<const float4*>(&g_x[a * 64]);
    const float4* zb = reinterpret_cast<const float4*>(&g_x[b * 64]);
    float4 u = za[sub * 2],     v = zb[sub * 2];
    float4 u2 = za[sub * 2 + 1], v2 = zb[sub * 2 + 1];
    float acc = u.x * v.x + u.y * v.y + u.z * v.z + u.w * v.w
              + u2.x * v2.x + u2.y * v2.y + u2.z * v2.z + u2.w * v2.w;
    acc += __shfl_xor_sync(0xffffffffu, acc, 4);
    acc += __shfl_xor_sync(0xffffffffu, acc, 2);
    acc += __shfl_xor_sync(0xffffffffu, acc, 1);
    if (sub == 0) out[e] = acc;
}

// ---------------- launch ----------------
extern "C" void kernel_launch(void* const* d_in, const int* in_sizes, int n_in,
                              void* d_out, int out_size)
{
    const int*   edge   = (const int*)d_in[0];
    const int*   rowi   = edge;
    const int*   coli   = edge + Ee;
    const int*   pe     = (const int*)d_in[1];
    const float* id_emb = (const float*)d_in[2];
    const float* n2v    = (const float*)d_in[3];
    const float* pw     = (const float*)d_in[4];
    const float* pb     = (const float*)d_in[5];
    const float* cw     = (const float*)d_in[6];
    const float* cb     = (const float*)d_in[7];
    const float* gamma  = (const float*)d_in[8];
    const float* beta   = (const float*)d_in[9];
    float*       out    = (float*)d_out;

    const int TB = 256;

    k_deg_init <<<(Nn + TB - 1) / TB, TB>>>();
    k_deg_count<<<(Ee + TB - 1) / TB, TB>>>(coli);
    k_deg_rsqrt<<<(Nn + TB - 1) / TB, TB>>>();

    // layer 0 (fused with projection)
    k_proj_gemm0<<<(Nn + 63) / 64, 256>>>(id_emb, n2v, pw, pb, cw, cb);
    k_scatter   <<<(Ee * 16 + TB - 1) / TB, TB>>>(rowi, coli);
    k_stats     <<<128, 256>>>(0);

    // layer 1 (BN-l0 fused into A-load)
    k_gemm_bn<<<(Nn + 63) / 64, 256>>>(cw + HID * HID, cb + HID, 0, gamma, beta);
    k_scatter<<<(Ee * 16 + TB - 1) / TB, TB>>>(rowi, coli);
    k_stats  <<<128, 256>>>(2 * HID);

    k_apply <<<(Nn * 16 + TB - 1) / TB, TB>>>(2 * HID, gamma + HID, beta + HID);
    k_decode<<<(EPn * 8 + TB - 1) / TB, TB>>>(pe, out);
}